// round 12
// baseline (speedup 1.0000x reference)
#include <cuda_runtime.h>
#include <cstdint>
#include <cstddef>

#define B_   8
#define T_   200
#define U_   50
#define V_   1024
#define UM1  (U_ - 1)

#define ROWS 311            // 62 ghost rows below, 200 data, 49 ghost above
#define PADW 64             // row width (cols 50..63 always zero)
#define SLAB (ROWS * PADW)  // 19904 floats per (batch, slab)

#define LN2   0.6931471805599453f
#define NEGINF (-1e30f)

// __device__ globals are zero-initialized; kernels only write data cells, so
// all margin rows/cols (and all skipped u > ui columns) stay exactly 0.
__device__ float g_blank[B_ * SLAB];   // linear probs, row 63+t, col u
__device__ float g_emit [B_ * SLAB];   // linear probs, row 62+t, col u+1
__device__ float g_res  [B_];
__device__ int   g_cnt  [B_];          // per-batch column arrivals (reset at end)
__device__ int   g_done;               // finished DP blocks       (reset at end)

__device__ __forceinline__ float lg2a(float x) {
    float r; asm("lg2.approx.f32 %0, %1;" : "=f"(r) : "f"(x)); return r;
}
__device__ __forceinline__ float rcpa(float x) {
    float r; asm("rcp.approx.f32 %0, %1;" : "=f"(r) : "f"(x)); return r;
}

// ---------------------------------------------------------------------------
// ONE fused kernel. 100 blocks x 256 threads, 159KB smem -> 1 block/SM,
// single wave (100 <= 148 SMs) so inter-block spin-waits cannot deadlock.
//  * warps 0-3 of every block: gather/softmax for 4 (b,u) columns, then
//    arrive on g_cnt[b] (threadfence + atomicAdd release pattern).
//  * blocks 0-7: DP for batch = blockIdx. Zero-fill ghost smem rows before
//    the gate, spin for all 50 columns of the batch, stage, run the
//    anti-diagonal wavefront (warp 0), publish g_res; the last finisher
//    computes the mean, writes out, and resets the counters for replay.
// ---------------------------------------------------------------------------
__global__ __launch_bounds__(256) void k_fused(const float* __restrict__ h,
                                               const int*   __restrict__ targets,
                                               const int*   __restrict__ ilen,
                                               const int*   __restrict__ tlen,
                                               float*       __restrict__ out) {
    extern __shared__ float smem[];
    const int tid  = threadIdx.x;
    const int wid  = tid >> 5;
    const int lane = tid & 31;
    const int bid  = blockIdx.x;

    // ================= LSE role (warps 0..3) =================
    if (wid < 4) {
        const int bu = bid * 4 + wid;                 // 0..399
        const int b  = bu / U_;
        const int u  = bu - b * U_;
        const int uiB = tlen[b] - 1;                  // [24,49]

        if (u <= uiB) {                               // reachable column
            const bool hasE = (u < uiB);
            const int  tgt  = hasE ? targets[b * UM1 + u] : 1;
            const float* base = h + ((size_t)(b * T_) * U_ + u) * V_;

            float vb[7], ve[7];
            #pragma unroll
            for (int k = 0; k < 7; ++k) {
                const int t = lane + 32 * k;
                const bool val = (t < T_);
                const float* p = base + (size_t)t * (U_ * V_);
                vb[k] = val ? __ldg(p) : NEGINF;
                ve[k] = (val && hasE) ? __ldg(p + tgt) : NEGINF;
            }

            float M0 = vb[0], M1 = ve[0];
            #pragma unroll
            for (int k = 1; k < 7; ++k) { M0 = fmaxf(M0, vb[k]); M1 = fmaxf(M1, ve[k]); }
            #pragma unroll
            for (int o = 16; o > 0; o >>= 1) {
                M0 = fmaxf(M0, __shfl_xor_sync(0xffffffffu, M0, o));
                M1 = fmaxf(M1, __shfl_xor_sync(0xffffffffu, M1, o));
            }

            float eb[7], ee[7], S0 = 0.0f, S1 = 0.0f;
            #pragma unroll
            for (int k = 0; k < 7; ++k) {
                eb[k] = __expf(vb[k] - M0); S0 += eb[k];
                ee[k] = __expf(ve[k] - M1); S1 += ee[k];
            }
            #pragma unroll
            for (int o = 16; o > 0; o >>= 1) {
                S0 += __shfl_xor_sync(0xffffffffu, S0, o);
                S1 += __shfl_xor_sync(0xffffffffu, S1, o);
            }
            const float r0 = rcpa(S0);
            const float r1 = rcpa(S1);

            float* gb = g_blank + b * SLAB;
            float* ge = g_emit  + b * SLAB;
            #pragma unroll
            for (int k = 0; k < 7; ++k) {
                const int t = lane + 32 * k;
                if (t < T_) {
                    gb[(63 + t) * PADW + u] = eb[k] * r0;
                    if (hasE) ge[(62 + t) * PADW + (u + 1)] = ee[k] * r1;
                }
            }
        }
        // arrive (even for skipped columns): release stores, then count
        __threadfence();
        __syncwarp();
        if (lane == 0) atomicAdd(&g_cnt[b], 1);
    }

    if (bid >= B_) return;          // non-DP blocks done (no further barriers)

    // ================= DP role (blocks 0..7, all 8 warps) =================
    float* sb = smem;               // [ROWS][PADW] blank slab
    float* se = smem + SLAB;        // [ROWS][PADW] emit slab
    {   // zero ghost rows BEFORE the gate (needs no data)
        float4* s4 = (float4*)smem;
        const float4 z4 = make_float4(0.f, 0.f, 0.f, 0.f);
        const int Q = SLAB / 4;
        for (int i = tid; i < 62 * 16; i += 256) { s4[i] = z4; s4[i + Q] = z4; }
        for (int i = tid; i < 48 * 16; i += 256) {
            s4[263 * 16 + i] = z4; s4[263 * 16 + Q + i] = z4;
        }
    }

    if (tid == 0) {                 // gate: all 50 columns of this batch
        while (((volatile int*)g_cnt)[bid] != U_) { }
        __threadfence();            // acquire
    }
    __syncthreads();

    {   // stage the 201 data rows of both slabs
        float4* s4 = (float4*)smem;
        const int Q = SLAB / 4;
        const float4* gb = (const float4*)(g_blank + bid * SLAB);
        const float4* ge = (const float4*)(g_emit  + bid * SLAB);
        #pragma unroll 4
        for (int i = tid; i < 201 * 16; i += 256) {
            s4[62 * 16 + i]     = gb[62 * 16 + i];
            s4[62 * 16 + Q + i] = ge[62 * 16 + i];
        }
    }
    __syncthreads();
    if (wid != 0) return;           // only warp 0 continues (no barriers below)

    const int ti = ilen[bid] - 1;   // [99, 199]
    const int ui = tlen[bid] - 1;   // [24, 49]
    const int dmax = ti + ui;

    int idx = (63 - 2 * lane) * PADW + 2 * lane;   // row of cell (t0,u0) at d=1

    float p0 = (lane == 0) ? 1.0f : 0.0f;          // alpha[0][0] = 1
    float p1 = 0.0f;
    int   L  = 0;                                  // warp-uniform frame exponent

    #define DP_STEP(o)                                                        \
    {                                                                         \
        const float lp  = __shfl_up_sync(0xffffffffu, p1, 1);                 \
        const float cbA = sb[o];                                              \
        const float ceA = se[o];                                              \
        const float cbB = sb[(o) - PADW + 1];                                 \
        const float ceB = se[(o) - PADW + 1];                                 \
        const float n0  = fmaf(p0, cbA, lp * ceA);                            \
        const float n1  = fmaf(p1, cbB, p0 * ceB);                            \
        p0 = n0; p1 = n1;                                                     \
    }

    const int ngroups = dmax >> 3;
    for (int g = 0; g < ngroups; ++g) {
        #pragma unroll
        for (int k = 0; k < 8; ++k) DP_STEP(idx + k * PADW)
        idx += 8 * PADW;

        // warp-uniform renorm from a reference active lane on diagonal dcur
        const int dcur = 8 * (g + 1);
        int lo = dcur - (T_ - 1);
        lo = (lo > 0) ? ((lo + 1) >> 1) : 0;
        const int hi  = min(ui >> 1, dcur >> 1);
        const int ref = (lo + hi) >> 1;

        float pr = __shfl_sync(0xffffffffu, p0, ref);
        pr = (pr > 0.0f) ? pr : 1.0f;
        const int e = (int)(__float_as_uint(pr) >> 23) - 127;
        L += e;
        const float fs = __uint_as_float((unsigned)(127 - e) << 23);  // 2^-e
        p0 *= fs; p1 *= fs;
    }

    const int tail = dmax & 7;
    for (int k = 0; k < tail; ++k) DP_STEP(idx + k * PADW)

    #undef DP_STEP

    // publish result; last finisher computes the mean and resets counters
    if (lane == (ui >> 1)) {
        const float pf = (ui & 1) ? p1 : p0;
        const float bf = sb[(63 + ti) * PADW + ui];
        g_res[bid] = -(lg2a(pf * bf) + (float)L) * LN2;
        __threadfence();
        const int old = atomicAdd(&g_done, 1);
        if (old == B_ - 1) {
            __threadfence();                       // acquire all g_res
            float s = 0.0f;
            #pragma unroll
            for (int i = 0; i < B_; ++i) s += g_res[i];
            out[0] = s * (1.0f / B_);
            #pragma unroll
            for (int i = 0; i < B_; ++i) g_cnt[i] = 0;   // reset for replay
            g_done = 0;
            __threadfence();
        }
    }
}

// ---------------------------------------------------------------------------
extern "C" void kernel_launch(void* const* d_in, const int* in_sizes, int n_in,
                              void* d_out, int out_size) {
    const float* h       = (const float*)d_in[0];
    const int*   targets = (const int*)  d_in[1];
    const int*   il      = (const int*)  d_in[2];
    const int*   tl      = (const int*)  d_in[3];
    float*       out     = (float*)d_out;

    const int smem_bytes = 2 * SLAB * (int)sizeof(float);  // 159232
    cudaFuncSetAttribute(k_fused, cudaFuncAttributeMaxDynamicSharedMemorySize,
                         smem_bytes);

    k_fused<<<100, 256, smem_bytes>>>(h, targets, il, tl, out);
}